// round 1
// baseline (speedup 1.0000x reference)
#include <cuda_runtime.h>

// Problem constants
#define BB 16
#define LL 2048
#define VV 64
#define CHUNK 128
#define NCHUNK (LL / CHUNK)

// Scratch (device globals: allocation-free)
__device__ float g_w[LL];       // w[d] = exp(v_emb[d])
__device__ float g_invD[LL];    // 1 / prefix_sum(w)[t]
__device__ float g_E[BB * VV * LL];  // E[b][c][s] = exp(P[b,c,s]), 8 MB

// -------- Kernel A: w = exp(v_emb), D = inclusive prefix sum, invD = 1/D ----
__global__ void kA(const float* __restrict__ v_emb) {
    __shared__ float sw[LL];
    __shared__ float warpTot[8];
    __shared__ float warpPre[8];
    int tid = threadIdx.x;  // 256 threads
    for (int i = tid; i < LL; i += 256) sw[i] = __expf(v_emb[i]);
    __syncthreads();

    // each thread scans 8 contiguous elements
    float vals[8];
    float run = 0.f;
    int base = tid * 8;
#pragma unroll
    for (int j = 0; j < 8; ++j) { run += sw[base + j]; vals[j] = run; }

    // warp-inclusive scan of chunk totals
    float x = run;
#pragma unroll
    for (int off = 1; off < 32; off <<= 1) {
        float y = __shfl_up_sync(0xffffffffu, x, off);
        if ((tid & 31) >= off) x += y;
    }
    if ((tid & 31) == 31) warpTot[tid >> 5] = x;
    __syncthreads();
    if (tid == 0) {
        float s = 0.f;
#pragma unroll
        for (int w = 0; w < 8; ++w) { float t2 = warpTot[w]; warpPre[w] = s; s += t2; }
    }
    __syncthreads();
    float pre = warpPre[tid >> 5] + (x - run);  // exclusive prefix of this thread's chunk
#pragma unroll
    for (int j = 0; j < 8; ++j) {
        float D = pre + vals[j];
        g_w[base + j] = sw[base + j];
        g_invD[base + j] = 1.0f / D;
    }
}

// degree-7 Taylor exp, accurate to <1e-7 rel for |x| <= 0.5 (here |x| <~ 0.1)
__device__ __forceinline__ float exp_poly(float x) {
    float r = 1.f / 5040.f;
    r = fmaf(r, x, 1.f / 720.f);
    r = fmaf(r, x, 1.f / 120.f);
    r = fmaf(r, x, 1.f / 24.f);
    r = fmaf(r, x, 1.f / 6.f);
    r = fmaf(r, x, 0.5f);
    r = fmaf(r, x, 1.f);
    r = fmaf(r, x, 1.f);
    return r;
}

// -------- Kernel B: per (b, t-chunk): buckets N[t][v] -> l1 -> P -> E --------
// N[b,t,v] = sum_{s<=t, idx[b,s]==v} w[t-s];  l1 = N * invD[t]
// P[b,c,t] = sum_v Wq[v,c] * l1[t,v];  E = exp(P) stored [b][c][t]
__global__ void __launch_bounds__(CHUNK) kB(const int* __restrict__ idx,
                                            const float* __restrict__ Wq) {
    extern __shared__ char smraw[];
    float* s_w    = (float*)smraw;                       // LL floats
    int*   s_idx  = (int*)(smraw + LL * 4);              // LL ints
    float* s_buck = (float*)(smraw + 2 * LL * 4);        // CHUNK*(VV+1)
    float* s_wq   = s_buck + CHUNK * (VV + 1);           // VV*VV (16B aligned)

    int chunk = blockIdx.x;
    int b     = blockIdx.y;
    int t0    = chunk * CHUNK;
    int t_end = t0 + CHUNK;
    int tid   = threadIdx.x;
    int t     = t0 + tid;

    for (int i = tid; i < t_end; i += CHUNK) {
        s_w[i]   = g_w[i];
        s_idx[i] = idx[b * LL + i];
    }
    for (int i = tid; i < VV * VV; i += CHUNK) s_wq[i] = Wq[i];

    float* myb = &s_buck[tid * (VV + 1)];
#pragma unroll
    for (int v = 0; v < VV; ++v) myb[v] = 0.f;
    __syncthreads();

    // Phase 1a: s < t0 -> every thread active (t >= t0 > s)
#pragma unroll 4
    for (int s = 0; s < t0; ++s) {
        int v = s_idx[s];
        myb[v] += s_w[t - s];
    }
    // Phase 1b: s in [t0, t_end) -> predicated on s <= t
#pragma unroll 4
    for (int s = t0; s < t_end; ++s) {
        int v = s_idx[s];
        int d = t - s;
        if (d >= 0) myb[v] += s_w[d];
    }

    // Phase 2: l1 row into registers
    float invd = g_invD[t];
    float l1r[VV];
#pragma unroll
    for (int v = 0; v < VV; ++v) l1r[v] = myb[v] * invd;

    // Phase 3: P = Wq^T . l1 over all 64 classes c; E = exp(P)
    size_t eb = (size_t)b * VV * LL;
#pragma unroll 1
    for (int cg = 0; cg < VV; cg += 4) {
        float a0 = 0.f, a1 = 0.f, a2 = 0.f, a3 = 0.f;
#pragma unroll
        for (int v = 0; v < VV; ++v) {
            float4 q = *(const float4*)&s_wq[v * VV + cg];  // broadcast across lanes
            a0 = fmaf(q.x, l1r[v], a0);
            a1 = fmaf(q.y, l1r[v], a1);
            a2 = fmaf(q.z, l1r[v], a2);
            a3 = fmaf(q.w, l1r[v], a3);
        }
        g_E[eb + (size_t)(cg + 0) * LL + t] = exp_poly(a0);
        g_E[eb + (size_t)(cg + 1) * LL + t] = exp_poly(a1);
        g_E[eb + (size_t)(cg + 2) * LL + t] = exp_poly(a2);
        g_E[eb + (size_t)(cg + 3) * LL + t] = exp_poly(a3);
    }
}

// -------- Kernel C: per (b,c) sequential scan over t ------------------------
// cum[t]   = sum_{s<=t} E[b,c,s]           (softmax denominator)
// acc_v[t] = sum_{s<=t, idx[b,s]==v} E[b,c,s]
// emit at each t with idx[b,t]==c: out[b,t,v] = Wv00 * acc_v / cum
__global__ void __launch_bounds__(64) kC(const int* __restrict__ idx,
                                         const float* __restrict__ Wv,
                                         float* __restrict__ out) {
    __shared__ float sE[LL];
    __shared__ int   sI[LL];
    int c = blockIdx.x;
    int b = blockIdx.y;
    int tid = threadIdx.x;  // tid = bucket v (0..63)

    const float* Ep = &g_E[((size_t)b * VV + c) * LL];
    for (int i = tid; i < LL; i += 64) {
        sE[i] = Ep[i];
        sI[i] = idx[b * LL + i];
    }
    __syncthreads();

    float wv00 = Wv[0];
    float acc = 0.f, cum = 0.f;
    float* ob = out + (size_t)b * LL * VV;

#pragma unroll 4
    for (int t = 0; t < LL; ++t) {
        float ev = sE[t];
        int   vt = sI[t];
        cum += ev;
        if (vt == tid) acc += ev;
        if (vt == c) {  // uniform across block
            ob[(size_t)t * VV + tid] = acc * __fdividef(wv00, cum);
        }
    }
}

extern "C" void kernel_launch(void* const* d_in, const int* in_sizes, int n_in,
                              void* d_out, int out_size) {
    const int*   idx   = (const int*)d_in[0];
    const float* Wq    = (const float*)d_in[1];
    const float* Wv    = (const float*)d_in[2];
    const float* v_emb = (const float*)d_in[3];
    float* out = (float*)d_out;

    kA<<<1, 256>>>(v_emb);

    size_t smemB = (size_t)LL * 4 * 2 + (size_t)CHUNK * (VV + 1) * 4 + (size_t)VV * VV * 4;
    cudaFuncSetAttribute(kB, cudaFuncAttributeMaxDynamicSharedMemorySize, (int)smemB);
    kB<<<dim3(NCHUNK, BB), CHUNK, smemB>>>(idx, Wq);

    kC<<<dim3(VV, BB), 64>>>(idx, Wv, out);
}

// round 2
// speedup vs baseline: 1.1843x; 1.1843x over previous
#include <cuda_runtime.h>

#define BB 16
#define LL 2048
#define VV 64
#define CHUNK 64
#define NCHUNK (LL / CHUNK)
#define BSTRIDE 68   // bucket row stride (floats): 16B-aligned rows, bank-spread

// Scratch: E[b][c][s] = exp(P[b,c,s]), 8 MB (L2-resident)
__device__ float g_E[(size_t)BB * VV * LL];

// degree-7 Taylor exp; |x| <= ~0.15 here -> rel err < 1e-9
__device__ __forceinline__ float exp_poly(float x) {
    float r = 1.f / 5040.f;
    r = fmaf(r, x, 1.f / 720.f);
    r = fmaf(r, x, 1.f / 120.f);
    r = fmaf(r, x, 1.f / 24.f);
    r = fmaf(r, x, 1.f / 6.f);
    r = fmaf(r, x, 0.5f);
    r = fmaf(r, x, 1.f);
    r = fmaf(r, x, 1.f);
    return r;
}

// ---------------------------------------------------------------------------
// Kernel B (fused A+B): per (b, t-chunk of 64):
//   w[d] = exp(v_emb[d]); D[t] = prefix(w); (computed locally per block)
//   N[t][v] = sum_{s<=t, idx[b,s]==v} w[t-s];  l1 = N * (1/D[t])
//   P[c,t] = sum_v Wq[v,c] * l1[t,v];  g_E[b][c][t] = exp(P)
// ---------------------------------------------------------------------------
__global__ void __launch_bounds__(CHUNK) kB(const int* __restrict__ idx,
                                            const float* __restrict__ Wq,
                                            const float* __restrict__ v_emb) {
    extern __shared__ char smraw[];
    float* s_w   = (float*)smraw;                                  // LL
    int*   s_idx = (int*)(smraw + LL * 4);                         // LL
    float* s_bk  = (float*)(smraw + 2 * LL * 4);                   // CHUNK*BSTRIDE
    float* s_wq  = (float*)(smraw + 2 * LL * 4 + CHUNK * BSTRIDE * 4); // VV*VV
    float* s_cb  = s_wq + VV * VV;                                 // CHUNK chunk-sum bases

    const int chunk = blockIdx.x;
    const int b     = blockIdx.y;
    const int t0    = chunk * CHUNK;
    const int t_end = t0 + CHUNK;
    const int tid   = threadIdx.x;
    const int t     = t0 + tid;

    // --- local kA: w = exp(v_emb) ---
    for (int i = tid; i < LL; i += CHUNK) s_w[i] = exp_poly(v_emb[i]);
    // idx for s < t_end only
    for (int i = tid; i < t_end; i += CHUNK) s_idx[i] = idx[b * LL + i];
    // Wq
    for (int i = tid; i < VV * VV; i += CHUNK) s_wq[i] = Wq[i];
    __syncthreads();

    // per-thread chunk sums of w (32 contiguous each), then exclusive bases
    {
        float tot = 0.f;
        const int cbase = tid * 32;
#pragma unroll
        for (int m = 0; m < 32; ++m) tot += s_w[cbase + m];
        s_cb[tid] = tot;
    }
    __syncthreads();
    float invd;
    {
        float base = 0.f;
        const int jt = t >> 5;
        for (int jj = 0; jj < jt; ++jj) base += s_cb[jj];
        const int off = t & 31;
        float D = base;
#pragma unroll 4
        for (int m = 0; m <= off; ++m) D += s_w[(jt << 5) + m];
        invd = 1.0f / D;
    }

    // zero my bucket row
    float4* row4 = (float4*)(s_bk + tid * BSTRIDE);
#pragma unroll
    for (int q = 0; q < VV / 4; ++q) row4[q] = make_float4(0.f, 0.f, 0.f, 0.f);
    __syncthreads();

    float* row = s_bk + tid * BSTRIDE;
    const float* wt = s_w + t;  // w[t - s] = wt[-s]

    // Phase 1a: s < t0 (all threads active); idx loaded as int4 (broadcast)
#pragma unroll 2
    for (int s = 0; s < t0; s += 4) {
        int4 v4 = *(const int4*)(s_idx + s);
        row[v4.x] += wt[-s];
        row[v4.y] += wt[-s - 1];
        row[v4.z] += wt[-s - 2];
        row[v4.w] += wt[-s - 3];
    }
    // Phase 1b: s in [t0, t] (causal tail)
    for (int s = t0; s <= t; ++s) row[s_idx[s]] += s_w[t - s];

    // Phase 2: l1 row into registers
    float l1r[VV];
#pragma unroll
    for (int v = 0; v < VV; ++v) l1r[v] = row[v] * invd;

    // Phase 3: P = Wq^T . l1 for all 64 classes, E = exp(P)
    float* eb = g_E + ((size_t)b * VV) * LL;
#pragma unroll 1
    for (int cg = 0; cg < VV; cg += 4) {
        float a0 = 0.f, a1 = 0.f, a2 = 0.f, a3 = 0.f;
#pragma unroll
        for (int v = 0; v < VV; ++v) {
            float4 q = *(const float4*)&s_wq[v * VV + cg];
            a0 = fmaf(q.x, l1r[v], a0);
            a1 = fmaf(q.y, l1r[v], a1);
            a2 = fmaf(q.z, l1r[v], a2);
            a3 = fmaf(q.w, l1r[v], a3);
        }
        eb[(size_t)(cg + 0) * LL + t] = exp_poly(a0);
        eb[(size_t)(cg + 1) * LL + t] = exp_poly(a1);
        eb[(size_t)(cg + 2) * LL + t] = exp_poly(a2);
        eb[(size_t)(cg + 3) * LL + t] = exp_poly(a3);
    }
}

// ---------------------------------------------------------------------------
// Kernel C: per (b,c), strip-parallel causal bucket scan over t.
//   thread j owns strip [32j, 32j+32)
//   pass 1: per-strip bucket sums + strip totals (1 scatter-add per element)
//   pass 2: exclusive prefix of buckets across strips (thread = v), cum bases
//   pass 3: rescan strip with bases; at idx[b,t]==c emit
//           out[b,t,v] = Wv00 * buck[v] / cum   (inclusive prefixes at t)
// ---------------------------------------------------------------------------
__global__ void __launch_bounds__(64) kC(const int* __restrict__ idx,
                                         const float* __restrict__ Wv,
                                         float* __restrict__ out) {
    __shared__ float s_bk[64 * BSTRIDE];
    __shared__ float s_tot[64];

    const int c   = blockIdx.x;
    const int b   = blockIdx.y;
    const int tid = threadIdx.x;   // strip id in passes 1/3, bucket v in pass 2

    const float* Ep = g_E + ((size_t)b * VV + c) * LL;
    const int*   Ip = idx + b * LL;
    const int    s0 = tid * 32;

    float* row = s_bk + tid * BSTRIDE;
    float4* row4 = (float4*)row;
#pragma unroll
    for (int q = 0; q < VV / 4; ++q) row4[q] = make_float4(0.f, 0.f, 0.f, 0.f);
    // no sync needed: pass 1 touches only own row

    // Pass 1: strip bucket sums
    float tot = 0.f;
#pragma unroll
    for (int k = 0; k < 32; k += 4) {
        float4 e = *(const float4*)(Ep + s0 + k);
        int4   v = *(const int4*)(Ip + s0 + k);
        row[v.x] += e.x;
        row[v.y] += e.y;
        row[v.z] += e.z;
        row[v.w] += e.w;
        tot += (e.x + e.y) + (e.z + e.w);
    }
    s_tot[tid] = tot;
    __syncthreads();

    // Pass 2: thread tid = bucket v; convert column v to exclusive prefixes
    {
        float run = 0.f;
#pragma unroll 8
        for (int jj = 0; jj < 64; ++jj) {
            float tv = s_bk[jj * BSTRIDE + tid];
            s_bk[jj * BSTRIDE + tid] = run;
            run += tv;
        }
    }
    // cum base for strip tid
    float cum = 0.f;
    for (int jj = 0; jj < tid; ++jj) cum += s_tot[jj];
    __syncthreads();

    // Pass 3: rescan strip; emit at idx==c
    const float wv00 = Wv[0];
    float* ob = out + (size_t)b * LL * VV;

#pragma unroll 1
    for (int k = 0; k < 32; k += 4) {
        float4 e = *(const float4*)(Ep + s0 + k);
        int4   v = *(const int4*)(Ip + s0 + k);

        cum += e.x; row[v.x] += e.x;
        if (v.x == c) {
            float sc = __fdividef(wv00, cum);
            float4* op = (float4*)(ob + (size_t)(s0 + k) * VV);
#pragma unroll
            for (int q = 0; q < VV / 4; ++q) {
                float4 x = row4[q];
                op[q] = make_float4(x.x * sc, x.y * sc, x.z * sc, x.w * sc);
            }
        }
        cum += e.y; row[v.y] += e.y;
        if (v.y == c) {
            float sc = __fdividef(wv00, cum);
            float4* op = (float4*)(ob + (size_t)(s0 + k + 1) * VV);
#pragma unroll
            for (int q = 0; q < VV / 4; ++q) {
                float4 x = row4[q];
                op[q] = make_float4(x.x * sc, x.y * sc, x.z * sc, x.w * sc);
            }
        }
        cum += e.z; row[v.z] += e.z;
        if (v.z == c) {
            float sc = __fdividef(wv00, cum);
            float4* op = (float4*)(ob + (size_t)(s0 + k + 2) * VV);
#pragma unroll
            for (int q = 0; q < VV / 4; ++q) {
                float4 x = row4[q];
                op[q] = make_float4(x.x * sc, x.y * sc, x.z * sc, x.w * sc);
            }
        }
        cum += e.w; row[v.w] += e.w;
        if (v.w == c) {
            float sc = __fdividef(wv00, cum);
            float4* op = (float4*)(ob + (size_t)(s0 + k + 3) * VV);
#pragma unroll
            for (int q = 0; q < VV / 4; ++q) {
                float4 x = row4[q];
                op[q] = make_float4(x.x * sc, x.y * sc, x.z * sc, x.w * sc);
            }
        }
    }
}

extern "C" void kernel_launch(void* const* d_in, const int* in_sizes, int n_in,
                              void* d_out, int out_size) {
    const int*   idx   = (const int*)d_in[0];
    const float* Wq    = (const float*)d_in[1];
    const float* Wv    = (const float*)d_in[2];
    const float* v_emb = (const float*)d_in[3];
    float* out = (float*)d_out;

    size_t smemB = (size_t)LL * 4 * 2 + (size_t)CHUNK * BSTRIDE * 4
                 + (size_t)VV * VV * 4 + (size_t)CHUNK * 4;
    static bool attr_set = false;
    if (!attr_set) {
        cudaFuncSetAttribute(kB, cudaFuncAttributeMaxDynamicSharedMemorySize, (int)smemB);
        attr_set = true;
    }
    kB<<<dim3(NCHUNK, BB), CHUNK, smemB>>>(idx, Wq, v_emb);
    kC<<<dim3(VV, BB), 64>>>(idx, Wv, out);
}

// round 4
// speedup vs baseline: 1.2297x; 1.0383x over previous
#include <cuda_runtime.h>

#define BB 16
#define LL 2048
#define VV 64
#define TB 128              // kB block = t-chunk size
#define NCHUNK (LL / TB)    // 16

// Scratch (device globals)
__device__ float g_E[(size_t)BB * VV * LL];          // exp(P[b,c,t]), 8 MB
__device__ unsigned short g_pos[BB * LL];            // positions sorted by (class, s)
__device__ int g_starts[BB * (VV + 1)];              // class segment starts

// degree-7 Taylor exp; |x| small here -> rel err < 1e-9
__device__ __forceinline__ float exp_poly(float x) {
    float r = 1.f / 5040.f;
    r = fmaf(r, x, 1.f / 720.f);
    r = fmaf(r, x, 1.f / 120.f);
    r = fmaf(r, x, 1.f / 24.f);
    r = fmaf(r, x, 1.f / 6.f);
    r = fmaf(r, x, 0.5f);
    r = fmaf(r, x, 1.f);
    r = fmaf(r, x, 1.f);
    return r;
}

// ---------------------------------------------------------------------------
// kS: stable counting sort of positions by class, per batch.
// 1024 threads, 2 elements each. Warp-level ranking via match_any.
// ---------------------------------------------------------------------------
__global__ void __launch_bounds__(1024) kS(const int* __restrict__ idx) {
    __shared__ int cnt[64][64];   // [virtual-warp][class]
    __shared__ int stot[64];
    __shared__ int sstart[64];

    const int b = blockIdx.x;
    const int tid = threadIdx.x;
    const int lane = tid & 31;

    for (int i = tid; i < 64 * 64; i += 1024) ((int*)cnt)[i] = 0;
    __syncthreads();

    int v0, lr0, v1, lr1;
    {
        int j = tid;
        v0 = idx[b * LL + j];
        unsigned m = __match_any_sync(0xffffffffu, v0);
        lr0 = __popc(m & ((1u << lane) - 1u));
        if (lr0 == 0) cnt[j >> 5][v0] = __popc(m);
    }
    {
        int j = tid + 1024;
        v1 = idx[b * LL + j];
        unsigned m = __match_any_sync(0xffffffffu, v1);
        lr1 = __popc(m & ((1u << lane) - 1u));
        if (lr1 == 0) cnt[j >> 5][v1] = __popc(m);
    }
    __syncthreads();

    if (tid < 64) {   // thread = class: exclusive prefix across virtual warps
        int run = 0;
        for (int vw = 0; vw < 64; ++vw) {
            int tv = cnt[vw][tid];
            cnt[vw][tid] = run;
            run += tv;
        }
        stot[tid] = run;
    }
    __syncthreads();
    if (tid < 64) {   // exclusive prefix across classes
        int st = 0;
        for (int u = 0; u < tid; ++u) st += stot[u];
        sstart[tid] = st;
        g_starts[b * 65 + tid] = st;
        if (tid == 63) g_starts[b * 65 + 64] = LL;
    }
    __syncthreads();

    g_pos[b * LL + sstart[v0] + cnt[(tid) >> 5][v0] + lr0] = (unsigned short)tid;
    g_pos[b * LL + sstart[v1] + cnt[(tid + 1024) >> 5][v1] + lr1] = (unsigned short)(tid + 1024);
}

// ---------------------------------------------------------------------------
// kB: per (b, t-chunk of 128):
//   w[d]=exp(v_emb[d]); invd = 1/prefix(w)[t]
//   l1r[v] = invd * sum_{p in list_v, p<=t} w[t-p]     (register accumulators)
//   P[c,t] = sum_v Wq[v,c]*l1r[v];  g_E[b][c][t] = exp(P)
// ---------------------------------------------------------------------------
__global__ void __launch_bounds__(TB) kB(const float* __restrict__ Wq,
                                         const float* __restrict__ v_emb) {
    __shared__ float s_wg[TB + LL];     // guard zeros + w
    __shared__ float s_wq[VV * VV];
    __shared__ unsigned short s_pos[LL];
    __shared__ int s_start[VV + 1];
    __shared__ int s_cut[VV];
    __shared__ float s_cb[TB];
    float* s_w = s_wg + TB;

    const int chunk = (NCHUNK - 1) - blockIdx.x;   // heavy chunks first
    const int b     = blockIdx.y;
    const int t0    = chunk * TB;
    const int t_end = t0 + TB;
    const int tid   = threadIdx.x;
    const int t     = t0 + tid;

    s_wg[tid] = 0.f;   // guard region (covers negative t-p down to -(TB-1))
    for (int i = tid; i < LL; i += TB) s_w[i] = exp_poly(v_emb[i]);
    for (int i = tid; i < VV * VV; i += TB) s_wq[i] = Wq[i];
    {   // vectorized position staging: 2048 u16 = 256 uint4
        const uint4* src = (const uint4*)(g_pos + b * LL);
        uint4* dst = (uint4*)s_pos;
        for (int i = tid; i < LL / 8; i += TB) dst[i] = src[i];
    }
    if (tid <= VV) s_start[tid] = g_starts[b * 65 + tid];
    __syncthreads();

    // per-v cutoff: first list index with pos >= t_end (binary search)
    if (tid < VV) {
        int lo = s_start[tid], hi = s_start[tid + 1];
        while (lo < hi) {
            int mid = (lo + hi) >> 1;
            if ((int)s_pos[mid] < t_end) lo = mid + 1; else hi = mid;
        }
        s_cut[tid] = lo;
    }
    // chunk sums for prefix of w
    {
        float tot = 0.f;
        const int cb = tid * (LL / TB);
#pragma unroll
        for (int m = 0; m < LL / TB; ++m) tot += s_w[cb + m];
        s_cb[tid] = tot;
    }
    __syncthreads();

    float invd;
    {
        const int jt = t >> 4;           // LL/TB == 16
        float D = 0.f;
        for (int jj = 0; jj < jt; ++jj) D += s_cb[jj];
        for (int m = jt << 4; m <= t; ++m) D += s_w[m];
        invd = 1.0f / D;
    }

    // Phase 1: gather bucket sums into registers (no smem RMW)
    float l1r[VV];
    const float* wt = s_w + t;           // w[t-p] = wt[-p]; guard zeros handle p>t
#pragma unroll
    for (int v = 0; v < VV; ++v) {
        int j    = s_start[v];
        int jend = s_cut[v];
        float a0 = 0.f, a1 = 0.f;
#pragma unroll 1
        for (; j + 1 < jend; j += 2) {
            int p0 = s_pos[j];
            int p1 = s_pos[j + 1];
            a0 += wt[-p0];
            a1 += wt[-p1];
        }
        if (j < jend) a0 += wt[-(int)s_pos[j]];
        l1r[v] = (a0 + a1) * invd;
    }

    // Phase 3: P = Wq^T . l1 for 64 classes; E = exp(P)
    float* eb = g_E + ((size_t)b * VV) * LL;
#pragma unroll 1
    for (int cg = 0; cg < VV; cg += 4) {
        float a0 = 0.f, a1 = 0.f, a2 = 0.f, a3 = 0.f;
#pragma unroll
        for (int v = 0; v < VV; ++v) {
            float4 q = *(const float4*)&s_wq[v * VV + cg];
            a0 = fmaf(q.x, l1r[v], a0);
            a1 = fmaf(q.y, l1r[v], a1);
            a2 = fmaf(q.z, l1r[v], a2);
            a3 = fmaf(q.w, l1r[v], a3);
        }
        eb[(size_t)(cg + 0) * LL + t] = exp_poly(a0);
        eb[(size_t)(cg + 1) * LL + t] = exp_poly(a1);
        eb[(size_t)(cg + 2) * LL + t] = exp_poly(a2);
        eb[(size_t)(cg + 3) * LL + t] = exp_poly(a3);
    }
}

// ---------------------------------------------------------------------------
// kC: per (b,c). Thread v walks list_v incrementally across the emit
// positions of class c. Denominator via block prefix-sum of E. No RMW.
// ---------------------------------------------------------------------------
__global__ void __launch_bounds__(64) kC(const float* __restrict__ Wv,
                                         float* __restrict__ out) {
    __shared__ float sE[LL];
    __shared__ float sP[LL];            // inclusive prefix of E
    __shared__ unsigned short spos[LL];
    __shared__ int sstart[VV + 1];
    __shared__ float stot[64];

    const int c   = blockIdx.x;
    const int b   = blockIdx.y;
    const int tid = threadIdx.x;        // = class v

    const float* Ep = g_E + ((size_t)b * VV + c) * LL;
    {
        const float4* src = (const float4*)Ep;
        float4* dst = (float4*)sE;
        for (int i = tid; i < LL / 4; i += 64) dst[i] = src[i];
        const uint4* psrc = (const uint4*)(g_pos + b * LL);
        uint4* pdst = (uint4*)spos;
        for (int i = tid; i < LL / 8; i += 64) pdst[i] = psrc[i];
    }
    // FIX (R3 bug): load ALL 65 entries — with 64 threads, `tid <= VV` missed
    // sstart[64], leaving pend/cend garbage for class 63 -> OOB spos/tk -> IMA.
    for (int i = tid; i <= VV; i += 64) sstart[i] = g_starts[b * 65 + i];
    __syncthreads();

    // prefix sum of E: strips of 32 per thread
    {
        const int s0 = tid * 32;
        float tot = 0.f;
#pragma unroll
        for (int m = 0; m < 32; ++m) tot += sE[s0 + m];
        stot[tid] = tot;
    }
    __syncthreads();
    {
        float base = 0.f;
        for (int jj = 0; jj < tid; ++jj) base += stot[jj];
        const int s0 = tid * 32;
#pragma unroll
        for (int m = 0; m < 32; ++m) { base += sE[s0 + m]; sP[s0 + m] = base; }
    }
    __syncthreads();

    const float wv00 = Wv[0];
    float* ob = out + (size_t)b * LL * VV;

    int ptr  = sstart[tid];
    int pend = sstart[tid + 1];
    float acc = 0.f;

    const int cbeg = sstart[c];
    const int cend = sstart[c + 1];
    for (int k = cbeg; k < cend; ++k) {
        const int tk = spos[k];         // broadcast; ascending over k
        while (ptr < pend) {
            int p = spos[ptr];
            if (p > tk) break;
            acc += sE[p];
            ++ptr;
        }
        float sc = __fdividef(wv00, sP[tk]);
        ob[(size_t)tk * VV + tid] = acc * sc;
    }
}

extern "C" void kernel_launch(void* const* d_in, const int* in_sizes, int n_in,
                              void* d_out, int out_size) {
    const int*   idx   = (const int*)d_in[0];
    const float* Wq    = (const float*)d_in[1];
    const float* Wv    = (const float*)d_in[2];
    const float* v_emb = (const float*)d_in[3];
    float* out = (float*)d_out;

    kS<<<BB, 1024>>>(idx);
    kB<<<dim3(NCHUNK, BB), TB>>>(Wq, v_emb);
    kC<<<dim3(VV, BB), 64>>>(Wv, out);
}

// round 5
// speedup vs baseline: 1.5576x; 1.2667x over previous
#include <cuda_runtime.h>

#define BB 16
#define LL 2048
#define VV 64
#define TB 128              // kB block = t-chunk size
#define NCHUNK (LL / TB)    // 16
#define PADL 2560           // padded position-list length (64 classes, 8-aligned)

// Scratch (device globals)
__device__ float g_E[(size_t)BB * VV * LL];      // exp(P[b,c,t]), 8 MB
__device__ unsigned short g_pos[BB * PADL];      // positions sorted by class, 8-aligned segs
__device__ int g_starts[BB * (VV + 1)];          // padded segment starts (8-aligned)
__device__ int g_cnt[BB * VV];                   // real counts per class

// degree-7 Taylor exp; |x| small here -> rel err < 1e-9
__device__ __forceinline__ float exp_poly(float x) {
    float r = 1.f / 5040.f;
    r = fmaf(r, x, 1.f / 720.f);
    r = fmaf(r, x, 1.f / 120.f);
    r = fmaf(r, x, 1.f / 24.f);
    r = fmaf(r, x, 1.f / 6.f);
    r = fmaf(r, x, 0.5f);
    r = fmaf(r, x, 1.f);
    r = fmaf(r, x, 1.f);
    return r;
}

// ---------------------------------------------------------------------------
// kS: stable counting sort of positions by class, per batch, with 8-aligned
// padded segments (pad sentinel = 2048 -> gathers exactly 0 via zero guard).
// ---------------------------------------------------------------------------
__global__ void __launch_bounds__(1024) kS(const int* __restrict__ idx) {
    __shared__ int cnt[64][64];   // [virtual-warp][class] -> later excl prefix
    __shared__ int stot[64];      // real count per class
    __shared__ int pstart[65];    // padded starts

    const int b = blockIdx.x;
    const int tid = threadIdx.x;
    const int lane = tid & 31;
    const int wid = tid >> 5;

    for (int i = tid; i < 64 * 64; i += 1024) ((int*)cnt)[i] = 0;
    __syncthreads();

    int v0, lr0, v1, lr1;
    {
        v0 = idx[b * LL + tid];
        unsigned m = __match_any_sync(0xffffffffu, v0);
        lr0 = __popc(m & ((1u << lane) - 1u));
        if (lr0 == 0) cnt[tid >> 5][v0] = __popc(m);
    }
    {
        int j = tid + 1024;
        v1 = idx[b * LL + j];
        unsigned m = __match_any_sync(0xffffffffu, v1);
        lr1 = __popc(m & ((1u << lane) - 1u));
        if (lr1 == 0) cnt[j >> 5][v1] = __popc(m);
    }
    __syncthreads();

    // Stage B: per class, exclusive prefix across 64 virtual warps.
    // Warp `wid` handles classes 2*wid and 2*wid+1 via shuffle scan.
#pragma unroll
    for (int cc = 0; cc < 2; ++cc) {
        int c = wid * 2 + cc;
        int a = cnt[2 * lane][c];
        int d = cnt[2 * lane + 1][c];
        int s = a + d;
        int x = s;
#pragma unroll
        for (int off = 1; off < 32; off <<= 1) {
            int y = __shfl_up_sync(0xffffffffu, x, off);
            if (lane >= off) x += y;
        }
        int e = x - s;  // exclusive
        cnt[2 * lane][c] = e;
        cnt[2 * lane + 1][c] = e + a;
        if (lane == 31) stot[c] = x;
    }
    __syncthreads();

    // Stage C: exclusive prefix of ceil8(counts) over 64 classes (warp 0).
    if (wid == 0) {
        int t0c = (stot[2 * lane] + 7) & ~7;
        int t1c = (stot[2 * lane + 1] + 7) & ~7;
        int s = t0c + t1c;
        int x = s;
#pragma unroll
        for (int off = 1; off < 32; off <<= 1) {
            int y = __shfl_up_sync(0xffffffffu, x, off);
            if (lane >= off) x += y;
        }
        int e = x - s;
        pstart[2 * lane] = e;
        pstart[2 * lane + 1] = e + t0c;
        if (lane == 31) pstart[64] = x;
    }
    __syncthreads();

    // Scatter positions
    g_pos[b * PADL + pstart[v0] + cnt[tid >> 5][v0] + lr0] = (unsigned short)tid;
    g_pos[b * PADL + pstart[v1] + cnt[(tid + 1024) >> 5][v1] + lr1] = (unsigned short)(tid + 1024);

    // Fill pads + metadata (disjoint slots, no sync needed)
    if (tid < 64) {
        for (int i = pstart[tid] + stot[tid]; i < pstart[tid + 1]; ++i)
            g_pos[b * PADL + i] = (unsigned short)LL;   // sentinel -> zero guard
        g_cnt[b * 64 + tid] = stot[tid];
        g_starts[b * 65 + tid] = pstart[tid];
        if (tid == 0) g_starts[b * 65 + 64] = pstart[64];
    }
}

// ---------------------------------------------------------------------------
// kB: per (b, t-chunk of 128):
//   w[d]=exp(v_emb[d]); invd = 1/prefix(w)[t]
//   l1r[v] = invd * sum_{p in list_v} w[t-p]    (8-wide MLP gather, reg accum,
//                                                zero guard handles p > t)
//   P[c,t] = sum_v Wq[v,c]*l1r[v];  g_E[b][c][t] = exp(P)
// ---------------------------------------------------------------------------
__global__ void __launch_bounds__(TB) kB(const float* __restrict__ Wq,
                                         const float* __restrict__ v_emb) {
    __shared__ float s_wg[2 * LL];        // LL guard zeros + LL w
    __shared__ float s_wq[VV * VV];
    __shared__ unsigned short s_pos[PADL];
    __shared__ int s_start[VV + 1];
    __shared__ int s_cut[VV];
    __shared__ float s_cb[TB];
    float* s_w = s_wg + LL;

    const int chunk = (NCHUNK - 1) - blockIdx.x;   // heavy chunks first
    const int b     = blockIdx.y;
    const int t0    = chunk * TB;
    const int t_end = t0 + TB;
    const int tid   = threadIdx.x;
    const int t     = t0 + tid;

    for (int i = tid; i < LL; i += TB) { s_wg[i] = 0.f; s_w[i] = exp_poly(v_emb[i]); }
    for (int i = tid; i < VV * VV; i += TB) s_wq[i] = Wq[i];
    {   // positions: 2560 u16 = 320 uint4
        const uint4* src = (const uint4*)(g_pos + b * PADL);
        uint4* dst = (uint4*)s_pos;
        for (int i = tid; i < PADL / 8; i += TB) dst[i] = src[i];
    }
    for (int i = tid; i <= VV; i += TB) s_start[i] = g_starts[b * 65 + i];
    __syncthreads();

    // per-v cutoff: first list index with pos >= t_end (pads are 2048 -> sorted last)
    if (tid < VV) {
        int lo = s_start[tid], hi = s_start[tid + 1];
        while (lo < hi) {
            int mid = (lo + hi) >> 1;
            if ((int)s_pos[mid] < t_end) lo = mid + 1; else hi = mid;
        }
        s_cut[tid] = lo;
    }
    // chunk sums (16 elems each) for prefix of w
    {
        float tot = 0.f;
        const int cb = tid * (LL / TB);
#pragma unroll
        for (int m = 0; m < LL / TB; ++m) tot += s_w[cb + m];
        s_cb[tid] = tot;
    }
    __syncthreads();

    float invd;
    {
        const int jt = t >> 4;           // 16 elems per chunk-sum
        float D = 0.f;
        for (int jj = 0; jj < jt; ++jj) D += s_cb[jj];
        for (int m = jt << 4; m <= t; ++m) D += s_w[m];
        invd = 1.0f / D;
    }

    // Phase 1: 8-wide gather into register accumulators. Positions beyond t
    // (including pads) read the zero guard -> contribute 0. No RMW, MLP=8.
    float l1r[VV];
    const float* wt = s_w + t;           // w[t-p] = wt[-p]
    const uint4* pos4 = (const uint4*)s_pos;
#pragma unroll
    for (int v = 0; v < VV; ++v) {
        int g    = s_start[v] >> 3;          // segment starts are 8-aligned
        int gend = (s_cut[v] + 7) >> 3;      // round up; extras are guard-zeros
        float a0 = 0.f, a1 = 0.f, a2 = 0.f, a3 = 0.f;
#pragma unroll 1
        for (; g < gend; ++g) {
            uint4 pk = pos4[g];
            a0 += wt[-(int)(pk.x & 0xffffu)];
            a1 += wt[-(int)(pk.x >> 16)];
            a2 += wt[-(int)(pk.y & 0xffffu)];
            a3 += wt[-(int)(pk.y >> 16)];
            a0 += wt[-(int)(pk.z & 0xffffu)];
            a1 += wt[-(int)(pk.z >> 16)];
            a2 += wt[-(int)(pk.w & 0xffffu)];
            a3 += wt[-(int)(pk.w >> 16)];
        }
        l1r[v] = ((a0 + a1) + (a2 + a3)) * invd;
    }

    // Phase 3: P = Wq^T . l1 for 64 classes; E = exp(P)
    float* eb = g_E + ((size_t)b * VV) * LL;
#pragma unroll 1
    for (int cg = 0; cg < VV; cg += 4) {
        float a0 = 0.f, a1 = 0.f, a2 = 0.f, a3 = 0.f;
#pragma unroll
        for (int v = 0; v < VV; ++v) {
            float4 q = *(const float4*)&s_wq[v * VV + cg];
            a0 = fmaf(q.x, l1r[v], a0);
            a1 = fmaf(q.y, l1r[v], a1);
            a2 = fmaf(q.z, l1r[v], a2);
            a3 = fmaf(q.w, l1r[v], a3);
        }
        eb[(size_t)(cg + 0) * LL + t] = exp_poly(a0);
        eb[(size_t)(cg + 1) * LL + t] = exp_poly(a1);
        eb[(size_t)(cg + 2) * LL + t] = exp_poly(a2);
        eb[(size_t)(cg + 3) * LL + t] = exp_poly(a3);
    }
}

// ---------------------------------------------------------------------------
// kC: per (b,c). Thread v walks list_v incrementally across the emit
// positions of class c. Denominator via shuffle-scan prefix of E.
// ---------------------------------------------------------------------------
__global__ void __launch_bounds__(64) kC(const float* __restrict__ Wv,
                                         float* __restrict__ out) {
    __shared__ float sE[LL];
    __shared__ float sP[LL];             // inclusive prefix of E
    __shared__ unsigned short spos[PADL];
    __shared__ int sstart[VV + 1];
    __shared__ int scnt[VV];
    __shared__ float wtot[2];

    const int c   = blockIdx.x;
    const int b   = blockIdx.y;
    const int tid = threadIdx.x;         // = class v
    const int lane = tid & 31, w = tid >> 5;

    const float* Ep = g_E + ((size_t)b * VV + c) * LL;
    {
        const float4* src = (const float4*)Ep;
        float4* dst = (float4*)sE;
        for (int i = tid; i < LL / 4; i += 64) dst[i] = src[i];
        const uint4* psrc = (const uint4*)(g_pos + b * PADL);
        uint4* pdst = (uint4*)spos;
        for (int i = tid; i < PADL / 8; i += 64) pdst[i] = psrc[i];
    }
    sstart[tid] = g_starts[b * 65 + tid];
    scnt[tid]   = g_cnt[b * 64 + tid];
    if (tid == 0) sstart[64] = g_starts[b * 65 + 64];
    __syncthreads();

    // prefix sum of E: strip of 32 per thread + shuffle scan of strip totals
    const int s0 = tid * 32;
    float tot = 0.f;
#pragma unroll
    for (int m = 0; m < 32; ++m) tot += sE[s0 + m];
    float x = tot;
#pragma unroll
    for (int off = 1; off < 32; off <<= 1) {
        float y = __shfl_up_sync(0xffffffffu, x, off);
        if (lane >= off) x += y;
    }
    if (lane == 31) wtot[w] = x;
    __syncthreads();
    float base = (x - tot) + (w ? wtot[0] : 0.f);
#pragma unroll
    for (int m = 0; m < 32; ++m) { base += sE[s0 + m]; sP[s0 + m] = base; }
    __syncthreads();

    const float wv00 = Wv[0];
    float* ob = out + (size_t)b * LL * VV;

    int ptr  = sstart[tid];
    const int pend = ptr + scnt[tid];    // real entries only (skip pads)
    float acc = 0.f;

    const int cbeg = sstart[c];
    const int cend = cbeg + scnt[c];
    for (int k = cbeg; k < cend; ++k) {
        const int tk = spos[k];          // broadcast; ascending over k
        while (ptr < pend) {
            int p = spos[ptr];
            if (p > tk) break;
            acc += sE[p];
            ++ptr;
        }
        float sc = __fdividef(wv00, sP[tk]);
        ob[(size_t)tk * VV + tid] = acc * sc;
    }
}

extern "C" void kernel_launch(void* const* d_in, const int* in_sizes, int n_in,
                              void* d_out, int out_size) {
    const int*   idx   = (const int*)d_in[0];
    const float* Wq    = (const float*)d_in[1];
    const float* Wv    = (const float*)d_in[2];
    const float* v_emb = (const float*)d_in[3];
    float* out = (float*)d_out;

    kS<<<BB, 1024>>>(idx);
    kB<<<dim3(NCHUNK, BB), TB>>>(Wq, v_emb);
    kC<<<dim3(VV, BB), 64>>>(Wv, out);
}

// round 6
// speedup vs baseline: 1.8382x; 1.1802x over previous
#include <cuda_runtime.h>

#define BB 16
#define LL 2048
#define VV 64
#define TB 64               // kB block = t-chunk size
#define NCHUNK (LL / TB)    // 32
#define PADL 2560           // padded position-list length (64 classes, 8-aligned)

// Scratch (device globals)
__device__ float g_E[(size_t)BB * VV * LL];      // exp(P[b,c,t]), 8 MB
__device__ unsigned short g_pos[BB * PADL];      // positions sorted by class, 8-aligned segs
__device__ int g_starts[BB * (VV + 1)];          // padded segment starts (8-aligned)
__device__ int g_cnt[BB * VV];                   // real counts per class

// degree-7 Taylor exp; |x| small here -> rel err < 1e-9
__device__ __forceinline__ float exp_poly(float x) {
    float r = 1.f / 5040.f;
    r = fmaf(r, x, 1.f / 720.f);
    r = fmaf(r, x, 1.f / 120.f);
    r = fmaf(r, x, 1.f / 24.f);
    r = fmaf(r, x, 1.f / 6.f);
    r = fmaf(r, x, 0.5f);
    r = fmaf(r, x, 1.f);
    r = fmaf(r, x, 1.f);
    return r;
}

// ---------------------------------------------------------------------------
// kS: stable counting sort of positions by class, per batch, 8-aligned padded
// segments (pad sentinel = 2048 -> hits zero guard in kB).
// cnt padded to [64][65] to kill the 32-way bank conflict seen in R5.
// ---------------------------------------------------------------------------
__global__ void __launch_bounds__(1024) kS(const int* __restrict__ idx) {
    __shared__ int cnt[64][65];   // [virtual-warp][class], padded stride
    __shared__ int stot[64];      // real count per class
    __shared__ int pstart[65];    // padded starts

    const int b = blockIdx.x;
    const int tid = threadIdx.x;
    const int lane = tid & 31;
    const int wid = tid >> 5;

    for (int i = tid; i < 64 * 65; i += 1024) ((int*)cnt)[i] = 0;
    __syncthreads();

    int v0, lr0, v1, lr1;
    {
        v0 = idx[b * LL + tid];
        unsigned m = __match_any_sync(0xffffffffu, v0);
        lr0 = __popc(m & ((1u << lane) - 1u));
        if (lr0 == 0) cnt[tid >> 5][v0] = __popc(m);
    }
    {
        int j = tid + 1024;
        v1 = idx[b * LL + j];
        unsigned m = __match_any_sync(0xffffffffu, v1);
        lr1 = __popc(m & ((1u << lane) - 1u));
        if (lr1 == 0) cnt[j >> 5][v1] = __popc(m);
    }
    __syncthreads();

    // Stage B: per class, exclusive prefix across 64 virtual warps (shuffle).
#pragma unroll
    for (int cc = 0; cc < 2; ++cc) {
        int c = wid * 2 + cc;
        int a = cnt[2 * lane][c];
        int d = cnt[2 * lane + 1][c];
        int s = a + d;
        int x = s;
#pragma unroll
        for (int off = 1; off < 32; off <<= 1) {
            int y = __shfl_up_sync(0xffffffffu, x, off);
            if (lane >= off) x += y;
        }
        int e = x - s;  // exclusive
        cnt[2 * lane][c] = e;
        cnt[2 * lane + 1][c] = e + a;
        if (lane == 31) stot[c] = x;
    }
    __syncthreads();

    // Stage C: exclusive prefix of ceil8(counts) over 64 classes (warp 0).
    if (wid == 0) {
        int t0c = (stot[2 * lane] + 7) & ~7;
        int t1c = (stot[2 * lane + 1] + 7) & ~7;
        int s = t0c + t1c;
        int x = s;
#pragma unroll
        for (int off = 1; off < 32; off <<= 1) {
            int y = __shfl_up_sync(0xffffffffu, x, off);
            if (lane >= off) x += y;
        }
        int e = x - s;
        pstart[2 * lane] = e;
        pstart[2 * lane + 1] = e + t0c;
        if (lane == 31) pstart[64] = x;
    }
    __syncthreads();

    // Scatter positions
    g_pos[b * PADL + pstart[v0] + cnt[tid >> 5][v0] + lr0] = (unsigned short)tid;
    g_pos[b * PADL + pstart[v1] + cnt[(tid + 1024) >> 5][v1] + lr1] = (unsigned short)(tid + 1024);

    // Pads + metadata (disjoint slots)
    if (tid < 64) {
        for (int i = pstart[tid] + stot[tid]; i < pstart[tid + 1]; ++i)
            g_pos[b * PADL + i] = (unsigned short)LL;   // sentinel -> zero guard
        g_cnt[b * 64 + tid] = stot[tid];
        g_starts[b * 65 + tid] = pstart[tid];
        if (tid == 0) g_starts[b * 65 + 64] = pstart[64];
    }
}

// ---------------------------------------------------------------------------
// kB: per (b, t-chunk of 64). Fused: for each class v,
//   gather  a = sum_{p in list_v} w[t-p]  (8-wide MLP, zero guard for p>t)
//   l1v = a * invd;  P[c] += Wq[v,c] * l1v  via packed fma.rn.f32x2 (FFMA2)
// then E[b][c][t] = exp(P[c]).
// ---------------------------------------------------------------------------
__global__ void __launch_bounds__(TB) kB(const float* __restrict__ Wq,
                                         const float* __restrict__ v_emb) {
    __shared__ __align__(16) float s_wg[2 * LL];   // LL guard zeros + LL w
    __shared__ __align__(16) float s_wq[VV * VV];
    __shared__ __align__(16) unsigned short s_pos[PADL];
    __shared__ int s_start[VV + 1];
    __shared__ int s_cut[VV];
    __shared__ float s_cb[TB];
    float* s_w = s_wg + LL;

    const int chunk = (NCHUNK - 1) - blockIdx.x;   // heavy chunks first
    const int b     = blockIdx.y;
    const int t0    = chunk * TB;
    const int t_end = t0 + TB;
    const int tid   = threadIdx.x;
    const int t     = t0 + tid;

    for (int i = tid; i < LL; i += TB) { s_wg[i] = 0.f; s_w[i] = exp_poly(v_emb[i]); }
    for (int i = tid; i < VV * VV; i += TB) s_wq[i] = Wq[i];
    {   // positions: 2560 u16 = 320 uint4
        const uint4* src = (const uint4*)(g_pos + b * PADL);
        uint4* dst = (uint4*)s_pos;
        for (int i = tid; i < PADL / 8; i += TB) dst[i] = src[i];
    }
    for (int i = tid; i <= VV; i += TB) s_start[i] = g_starts[b * 65 + i];
    __syncthreads();

    // per-v cutoff: first list index with pos >= t_end (pads sort last)
    if (tid < VV) {
        int lo = s_start[tid], hi = s_start[tid + 1];
        while (lo < hi) {
            int mid = (lo + hi) >> 1;
            if ((int)s_pos[mid] < t_end) lo = mid + 1; else hi = mid;
        }
        s_cut[tid] = lo;
    }
    // chunk sums (32 elems each) for prefix of w
    {
        float tot = 0.f;
        const int cb = tid * (LL / TB);
#pragma unroll
        for (int m = 0; m < LL / TB; ++m) tot += s_w[cb + m];
        s_cb[tid] = tot;
    }
    __syncthreads();

    float invd;
    {
        const int jt = t >> 5;           // 32 elems per chunk-sum
        float D = 0.f;
        for (int jj = 0; jj < jt; ++jj) D += s_cb[jj];
        for (int m = jt << 5; m <= t; ++m) D += s_w[m];
        invd = 1.0f / D;
    }

    // Fused gather + FFMA2 accumulation. P[c] pairs live in 32 b64 regs.
    unsigned long long acc[VV / 2];
#pragma unroll
    for (int i = 0; i < VV / 2; ++i) acc[i] = 0ull;

    const float* wt = s_w + t;           // w[t-p] = wt[-p]
    const uint4* pos4 = (const uint4*)s_pos;

#pragma unroll 1
    for (int v = 0; v < VV; ++v) {
        int g    = s_start[v] >> 3;          // segment starts are 8-aligned
        int gend = (s_cut[v] + 7) >> 3;      // extras hit guard zeros
        float a0 = 0.f, a1 = 0.f, a2 = 0.f, a3 = 0.f;
#pragma unroll 2
        for (; g < gend; ++g) {
            uint4 pk = pos4[g];
            a0 += wt[-(int)(pk.x & 0xffffu)];
            a1 += wt[-(int)(pk.x >> 16)];
            a2 += wt[-(int)(pk.y & 0xffffu)];
            a3 += wt[-(int)(pk.y >> 16)];
            a0 += wt[-(int)(pk.z & 0xffffu)];
            a1 += wt[-(int)(pk.z >> 16)];
            a2 += wt[-(int)(pk.w & 0xffffu)];
            a3 += wt[-(int)(pk.w >> 16)];
        }
        float l1v = ((a0 + a1) + (a2 + a3)) * invd;

        unsigned long long lv2;
        asm("mov.b64 %0, {%1, %1};" : "=l"(lv2) : "r"(__float_as_uint(l1v)));

        const double2* qrow = (const double2*)&s_wq[v * VV];  // row v over c
#pragma unroll
        for (int i = 0; i < VV / 4; ++i) {
            double2 q = qrow[i];   // LDS.128 -> two b64 halves, no repack
            unsigned long long q0 = __double_as_longlong(q.x);
            unsigned long long q1 = __double_as_longlong(q.y);
            asm("fma.rn.f32x2 %0, %1, %2, %0;" : "+l"(acc[2 * i])     : "l"(q0), "l"(lv2));
            asm("fma.rn.f32x2 %0, %1, %2, %0;" : "+l"(acc[2 * i + 1]) : "l"(q1), "l"(lv2));
        }
    }

    // Epilogue: E = exp(P), stores coalesced over t
    float* eb = g_E + ((size_t)b * VV) * LL;
#pragma unroll
    for (int i = 0; i < VV / 2; ++i) {
        unsigned lo, hi;
        asm("mov.b64 {%0, %1}, %2;" : "=r"(lo), "=r"(hi) : "l"(acc[i]));
        eb[(size_t)(2 * i) * LL + t]     = exp_poly(__uint_as_float(lo));
        eb[(size_t)(2 * i + 1) * LL + t] = exp_poly(__uint_as_float(hi));
    }
}

// ---------------------------------------------------------------------------
// kC: per (b,c). Thread v walks list_v incrementally across the emit
// positions of class c. Denominator via shuffle-scan prefix of E.
// ---------------------------------------------------------------------------
__global__ void __launch_bounds__(64) kC(const float* __restrict__ Wv,
                                         float* __restrict__ out) {
    __shared__ __align__(16) float sE[LL];
    __shared__ float sP[LL];             // inclusive prefix of E
    __shared__ __align__(16) unsigned short spos[PADL];
    __shared__ int sstart[VV + 1];
    __shared__ int scnt[VV];
    __shared__ float wtot[2];

    const int c   = blockIdx.x;
    const int b   = blockIdx.y;
    const int tid = threadIdx.x;         // = class v
    const int lane = tid & 31, w = tid >> 5;

    const float* Ep = g_E + ((size_t)b * VV + c) * LL;
    {
        const float4* src = (const float4*)Ep;
        float4* dst = (float4*)sE;
        for (int i = tid; i < LL / 4; i += 64) dst[i] = src[i];
        const uint4* psrc = (const uint4*)(g_pos + b * PADL);
        uint4* pdst = (uint4*)spos;
        for (int i = tid; i < PADL / 8; i += 64) pdst[i] = psrc[i];
    }
    sstart[tid] = g_starts[b * 65 + tid];
    scnt[tid]   = g_cnt[b * 64 + tid];
    if (tid == 0) sstart[64] = g_starts[b * 65 + 64];
    __syncthreads();

    // prefix sum of E: strip of 32 per thread + shuffle scan of strip totals
    const int s0 = tid * 32;
    float tot = 0.f;
#pragma unroll
    for (int m = 0; m < 32; ++m) tot += sE[s0 + m];
    float x = tot;
#pragma unroll
    for (int off = 1; off < 32; off <<= 1) {
        float y = __shfl_up_sync(0xffffffffu, x, off);
        if (lane >= off) x += y;
    }
    if (lane == 31) wtot[w] = x;
    __syncthreads();
    float base = (x - tot) + (w ? wtot[0] : 0.f);
#pragma unroll
    for (int m = 0; m < 32; ++m) { base += sE[s0 + m]; sP[s0 + m] = base; }
    __syncthreads();

    const float wv00 = Wv[0];
    float* ob = out + (size_t)b * LL * VV;

    int ptr  = sstart[tid];
    const int pend = ptr + scnt[tid];    // real entries only (skip pads)
    float acc = 0.f;

    const int cbeg = sstart[c];
    const int cend = cbeg + scnt[c];
    for (int k = cbeg; k < cend; ++k) {
        const int tk = spos[k];          // broadcast; ascending over k
        while (ptr < pend) {
            int p = spos[ptr];
            if (p > tk) break;
            acc += sE[p];
            ++ptr;
        }
        float sc = __fdividef(wv00, sP[tk]);
        ob[(size_t)tk * VV + tid] = acc * sc;
    }
}

extern "C" void kernel_launch(void* const* d_in, const int* in_sizes, int n_in,
                              void* d_out, int out_size) {
    const int*   idx   = (const int*)d_in[0];
    const float* Wq    = (const float*)d_in[1];
    const float* Wv    = (const float*)d_in[2];
    const float* v_emb = (const float*)d_in[3];
    float* out = (float*)d_out;

    kS<<<BB, 1024>>>(idx);
    kB<<<dim3(NCHUNK, BB), TB>>>(Wq, v_emb);
    kC<<<dim3(VV, BB), 64>>>(Wv, out);
}

// round 7
// speedup vs baseline: 2.1966x; 1.1950x over previous
#include <cuda_runtime.h>

#define BB 16
#define LL 2048
#define VV 64
#define TB 64               // t's per kB block
#define NVG 8               // v-groups per block
#define KBT (TB * NVG)      // 512 threads
#define NCHUNK (LL / TB)    // 32
#define PADL 2560           // padded position-list length (64 classes, 8-aligned)

// Scratch (device globals)
__device__ float g_E[(size_t)BB * VV * LL];      // exp(P[b,c,t]), 8 MB
__device__ unsigned short g_pos[BB * PADL];      // positions sorted by class, 8-aligned segs
__device__ int g_starts[BB * (VV + 1)];          // padded segment starts (8-aligned)
__device__ int g_cnt[BB * VV];                   // real counts per class

// degree-7 Taylor exp; |x| small here -> rel err < 1e-9
__device__ __forceinline__ float exp_poly(float x) {
    float r = 1.f / 5040.f;
    r = fmaf(r, x, 1.f / 720.f);
    r = fmaf(r, x, 1.f / 120.f);
    r = fmaf(r, x, 1.f / 24.f);
    r = fmaf(r, x, 1.f / 6.f);
    r = fmaf(r, x, 0.5f);
    r = fmaf(r, x, 1.f);
    r = fmaf(r, x, 1.f);
    return r;
}

// ---------------------------------------------------------------------------
// kS: stable counting sort of positions by class, per batch (unchanged R6).
// ---------------------------------------------------------------------------
__global__ void __launch_bounds__(1024) kS(const int* __restrict__ idx) {
    __shared__ int cnt[64][65];
    __shared__ int stot[64];
    __shared__ int pstart[65];

    const int b = blockIdx.x;
    const int tid = threadIdx.x;
    const int lane = tid & 31;
    const int wid = tid >> 5;

    for (int i = tid; i < 64 * 65; i += 1024) ((int*)cnt)[i] = 0;
    __syncthreads();

    int v0, lr0, v1, lr1;
    {
        v0 = idx[b * LL + tid];
        unsigned m = __match_any_sync(0xffffffffu, v0);
        lr0 = __popc(m & ((1u << lane) - 1u));
        if (lr0 == 0) cnt[tid >> 5][v0] = __popc(m);
    }
    {
        int j = tid + 1024;
        v1 = idx[b * LL + j];
        unsigned m = __match_any_sync(0xffffffffu, v1);
        lr1 = __popc(m & ((1u << lane) - 1u));
        if (lr1 == 0) cnt[j >> 5][v1] = __popc(m);
    }
    __syncthreads();

#pragma unroll
    for (int cc = 0; cc < 2; ++cc) {
        int c = wid * 2 + cc;
        int a = cnt[2 * lane][c];
        int d = cnt[2 * lane + 1][c];
        int s = a + d;
        int x = s;
#pragma unroll
        for (int off = 1; off < 32; off <<= 1) {
            int y = __shfl_up_sync(0xffffffffu, x, off);
            if (lane >= off) x += y;
        }
        int e = x - s;
        cnt[2 * lane][c] = e;
        cnt[2 * lane + 1][c] = e + a;
        if (lane == 31) stot[c] = x;
    }
    __syncthreads();

    if (wid == 0) {
        int t0c = (stot[2 * lane] + 7) & ~7;
        int t1c = (stot[2 * lane + 1] + 7) & ~7;
        int s = t0c + t1c;
        int x = s;
#pragma unroll
        for (int off = 1; off < 32; off <<= 1) {
            int y = __shfl_up_sync(0xffffffffu, x, off);
            if (lane >= off) x += y;
        }
        int e = x - s;
        pstart[2 * lane] = e;
        pstart[2 * lane + 1] = e + t0c;
        if (lane == 31) pstart[64] = x;
    }
    __syncthreads();

    g_pos[b * PADL + pstart[v0] + cnt[tid >> 5][v0] + lr0] = (unsigned short)tid;
    g_pos[b * PADL + pstart[v1] + cnt[(tid + 1024) >> 5][v1] + lr1] = (unsigned short)(tid + 1024);

    if (tid < 64) {
        for (int i = pstart[tid] + stot[tid]; i < pstart[tid + 1]; ++i)
            g_pos[b * PADL + i] = (unsigned short)LL;
        g_cnt[b * 64 + tid] = stot[tid];
        g_starts[b * 65 + tid] = pstart[tid];
        if (tid == 0) g_starts[b * 65 + 64] = pstart[64];
    }
}

// ---------------------------------------------------------------------------
// kB: 512 threads = 64 t x 8 v-groups.
//  Phase A: thread (tt,vg) gathers classes [8vg,8vg+8): l1[v][tt] to smem.
//  Phase B: thread (tt,cg) accumulates P[c] for 8 classes over all 64 v via
//           FFMA2 (Wq rows warp-broadcast LDS.128), then E = exp(P) -> gmem.
// ---------------------------------------------------------------------------
__global__ void __launch_bounds__(KBT) kB(const float* __restrict__ Wq,
                                          const float* __restrict__ v_emb) {
    extern __shared__ __align__(16) char smraw[];
    float* s_wg   = (float*)smraw;                       // 2*LL (guard + w)
    float* s_wq   = s_wg + 2 * LL;                       // VV*VV
    float* s_l1   = s_wq + VV * VV;                      // VV*TB, [v][tt]
    unsigned short* s_pos = (unsigned short*)(s_l1 + VV * TB);  // PADL
    int*   s_start = (int*)(s_pos + PADL);               // 65
    int*   s_cut   = s_start + 65;                       // 64
    float* s_cbp   = (float*)(s_cut + 64);               // 64 (inclusive chunk prefix)
    float* s_invd  = s_cbp + 64;                         // 64
    float* s_wtot  = s_invd + 64;                        // 2
    float* s_w = s_wg + LL;

    const int chunk = (NCHUNK - 1) - blockIdx.x;         // heavy chunks first
    const int b     = blockIdx.y;
    const int t0    = chunk * TB;
    const int t_end = t0 + TB;
    const int tid   = threadIdx.x;

    for (int i = tid; i < LL; i += KBT) { s_wg[i] = 0.f; s_w[i] = exp_poly(v_emb[i]); }
    for (int i = tid; i < VV * VV; i += KBT) s_wq[i] = Wq[i];
    {
        const uint4* src = (const uint4*)(g_pos + b * PADL);
        uint4* dst = (uint4*)s_pos;
        for (int i = tid; i < PADL / 8; i += KBT) dst[i] = src[i];
    }
    for (int i = tid; i <= VV; i += KBT) s_start[i] = g_starts[b * 65 + i];
    __syncthreads();

    // --- tid<64 housekeeping: cutoffs, chunk-sum scan, invd ---
    float cbx = 0.f;
    if (tid < 64) {
        // binary search cutoff for class tid
        int lo = s_start[tid], hi = s_start[tid + 1];
        while (lo < hi) {
            int mid = (lo + hi) >> 1;
            if ((int)s_pos[mid] < t_end) lo = mid + 1; else hi = mid;
        }
        s_cut[tid] = lo;
        // 32-elem chunk sum + warp shuffle scan
        float cb = 0.f;
        const int cb0 = tid * 32;
#pragma unroll
        for (int m = 0; m < 32; ++m) cb += s_w[cb0 + m];
        cbx = cb;
#pragma unroll
        for (int off = 1; off < 32; off <<= 1) {
            float y = __shfl_up_sync(0xffffffffu, cbx, off);
            if ((tid & 31) >= off) cbx += y;
        }
        if ((tid & 31) == 31) s_wtot[tid >> 5] = cbx;
    }
    __syncthreads();
    if (tid < 64) {
        s_cbp[tid] = cbx + ((tid >> 5) ? s_wtot[0] : 0.f);
    }
    __syncthreads();
    if (tid < 64) {
        const int t = t0 + tid;
        const int jt = t >> 5;
        float D = jt ? s_cbp[jt - 1] : 0.f;
        for (int m = jt << 5; m <= t; ++m) D += s_w[m];
        s_invd[tid] = 1.0f / D;
    }
    __syncthreads();

    // --- Phase A: gather 8 classes per thread ---
    const int tt = tid & (TB - 1);
    const int vg = tid >> 6;            // 0..7
    const int t  = t0 + tt;
    {
        const float invd = s_invd[tt];
        const float* wt = s_w + t;      // w[t-p] = wt[-p]; guard zeros for p>t
        const uint4* pos4 = (const uint4*)s_pos;
#pragma unroll
        for (int vs = 0; vs < 8; ++vs) {
            const int v = vg * 8 + vs;
            int g    = s_start[v] >> 3;
            int gend = (s_cut[v] + 7) >> 3;
            float a0 = 0.f, a1 = 0.f, a2 = 0.f, a3 = 0.f;
#pragma unroll 2
            for (; g < gend; ++g) {
                uint4 pk = pos4[g];
                a0 += wt[-(int)(pk.x & 0xffffu)];
                a1 += wt[-(int)(pk.x >> 16)];
                a2 += wt[-(int)(pk.y & 0xffffu)];
                a3 += wt[-(int)(pk.y >> 16)];
                a0 += wt[-(int)(pk.z & 0xffffu)];
                a1 += wt[-(int)(pk.z >> 16)];
                a2 += wt[-(int)(pk.w & 0xffffu)];
                a3 += wt[-(int)(pk.w >> 16)];
            }
            s_l1[v * TB + tt] = ((a0 + a1) + (a2 + a3)) * invd;
        }
    }
    __syncthreads();

    // --- Phase B: P[c] for 8 classes (cg = vg) over all 64 v, FFMA2 ---
    const int cg = vg;
    unsigned long long acc0 = 0ull, acc1 = 0ull, acc2 = 0ull, acc3 = 0ull;
#pragma unroll 8
    for (int v = 0; v < VV; ++v) {
        float lv = s_l1[v * TB + tt];
        unsigned long long lv2;
        asm("mov.b64 %0, {%1, %1};" : "=l"(lv2) : "r"(__float_as_uint(lv)));
        const double2* q = (const double2*)&s_wq[v * VV + cg * 8];
        double2 qa = q[0];               // c pairs (0,1),(2,3)
        double2 qb = q[1];               // c pairs (4,5),(6,7)
        unsigned long long w0 = __double_as_longlong(qa.x);
        unsigned long long w1 = __double_as_longlong(qa.y);
        unsigned long long w2 = __double_as_longlong(qb.x);
        unsigned long long w3 = __double_as_longlong(qb.y);
        asm("fma.rn.f32x2 %0, %1, %2, %0;" : "+l"(acc0) : "l"(w0), "l"(lv2));
        asm("fma.rn.f32x2 %0, %1, %2, %0;" : "+l"(acc1) : "l"(w1), "l"(lv2));
        asm("fma.rn.f32x2 %0, %1, %2, %0;" : "+l"(acc2) : "l"(w2), "l"(lv2));
        asm("fma.rn.f32x2 %0, %1, %2, %0;" : "+l"(acc3) : "l"(w3), "l"(lv2));
    }

    // Epilogue: E = exp(P); stores coalesced over t
    float* eb = g_E + ((size_t)b * VV + cg * 8) * LL + t;
    {
        unsigned lo, hi;
        asm("mov.b64 {%0, %1}, %2;" : "=r"(lo), "=r"(hi) : "l"(acc0));
        eb[0 * LL] = exp_poly(__uint_as_float(lo));
        eb[1 * LL] = exp_poly(__uint_as_float(hi));
        asm("mov.b64 {%0, %1}, %2;" : "=r"(lo), "=r"(hi) : "l"(acc1));
        eb[2 * LL] = exp_poly(__uint_as_float(lo));
        eb[3 * LL] = exp_poly(__uint_as_float(hi));
        asm("mov.b64 {%0, %1}, %2;" : "=r"(lo), "=r"(hi) : "l"(acc2));
        eb[4 * LL] = exp_poly(__uint_as_float(lo));
        eb[5 * LL] = exp_poly(__uint_as_float(hi));
        asm("mov.b64 {%0, %1}, %2;" : "=r"(lo), "=r"(hi) : "l"(acc3));
        eb[6 * LL] = exp_poly(__uint_as_float(lo));
        eb[7 * LL] = exp_poly(__uint_as_float(hi));
    }
}

// ---------------------------------------------------------------------------
// kC: per (b,c). Thread v walks list_v incrementally across the emit
// positions of class c (unchanged R6).
// ---------------------------------------------------------------------------
__global__ void __launch_bounds__(64) kC(const float* __restrict__ Wv,
                                         float* __restrict__ out) {
    __shared__ __align__(16) float sE[LL];
    __shared__ float sP[LL];
    __shared__ __align__(16) unsigned short spos[PADL];
    __shared__ int sstart[VV + 1];
    __shared__ int scnt[VV];
    __shared__ float wtot[2];

    const int c   = blockIdx.x;
    const int b   = blockIdx.y;
    const int tid = threadIdx.x;
    const int lane = tid & 31, w = tid >> 5;

    const float* Ep = g_E + ((size_t)b * VV + c) * LL;
    {
        const float4* src = (const float4*)Ep;
        float4* dst = (float4*)sE;
        for (int i = tid; i < LL / 4; i += 64) dst[i] = src[i];
        const uint4* psrc = (const uint4*)(g_pos + b * PADL);
        uint4* pdst = (uint4*)spos;
        for (int i = tid; i < PADL / 8; i += 64) pdst[i] = psrc[i];
    }
    sstart[tid] = g_starts[b * 65 + tid];
    scnt[tid]   = g_cnt[b * 64 + tid];
    if (tid == 0) sstart[64] = g_starts[b * 65 + 64];
    __syncthreads();

    const int s0 = tid * 32;
    float tot = 0.f;
#pragma unroll
    for (int m = 0; m < 32; ++m) tot += sE[s0 + m];
    float x = tot;
#pragma unroll
    for (int off = 1; off < 32; off <<= 1) {
        float y = __shfl_up_sync(0xffffffffu, x, off);
        if (lane >= off) x += y;
    }
    if (lane == 31) wtot[w] = x;
    __syncthreads();
    float base = (x - tot) + (w ? wtot[0] : 0.f);
#pragma unroll
    for (int m = 0; m < 32; ++m) { base += sE[s0 + m]; sP[s0 + m] = base; }
    __syncthreads();

    const float wv00 = Wv[0];
    float* ob = out + (size_t)b * LL * VV;

    int ptr  = sstart[tid];
    const int pend = ptr + scnt[tid];
    float acc = 0.f;

    const int cbeg = sstart[c];
    const int cend = cbeg + scnt[c];
    for (int k = cbeg; k < cend; ++k) {
        const int tk = spos[k];
        while (ptr < pend) {
            int p = spos[ptr];
            if (p > tk) break;
            acc += sE[p];
            ++ptr;
        }
        float sc = __fdividef(wv00, sP[tk]);
        ob[(size_t)tk * VV + tid] = acc * sc;
    }
}

extern "C" void kernel_launch(void* const* d_in, const int* in_sizes, int n_in,
                              void* d_out, int out_size) {
    const int*   idx   = (const int*)d_in[0];
    const float* Wq    = (const float*)d_in[1];
    const float* Wv    = (const float*)d_in[2];
    const float* v_emb = (const float*)d_in[3];
    float* out = (float*)d_out;

    size_t smemB = (size_t)(2 * LL) * 4 + (size_t)VV * VV * 4 + (size_t)VV * TB * 4
                 + (size_t)PADL * 2 + (65 + 64) * 4 + (64 + 64 + 2) * 4;
    cudaFuncSetAttribute(kB, cudaFuncAttributeMaxDynamicSharedMemorySize, (int)smemB);

    kS<<<BB, 1024>>>(idx);
    kB<<<dim3(NCHUNK, BB), KBT, smemB>>>(Wq, v_emb);
    kC<<<dim3(VV, BB), 64>>>(Wv, out);
}